// round 1
// baseline (speedup 1.0000x reference)
#include <cuda_runtime.h>
#include <math.h>

#define NN 50000
#define EE 1600000
#define VV 100000
#define DD 128
#define OO 64
#define TOT (NN*16)

// ---------------- scratch (static device globals; no allocs allowed) ----------
__device__ int   g_cnt[NN];
__device__ int   g_offs[NN + 1];
__device__ int   g_csr[EE];
__device__ float g_isqrt[NN];
__device__ float g_dinv[NN];
__device__ float g_x[NN * DD];   // embedding output / reused as mu|ls concat
__device__ float g_p[NN * DD];   // aggregation output (p1, then p2)
__device__ float g_h[NN * DD];   // relu(gemm1)
__device__ float g_z[NN * OO];

// ---------------- small utility kernels --------------------------------------
__global__ void k_zero_cnt() {
    int i = blockIdx.x * blockDim.x + threadIdx.x;
    if (i < NN) g_cnt[i] = 0;
}

__global__ void k_hist(const int* __restrict__ dst) {
    int e = blockIdx.x * blockDim.x + threadIdx.x;
    if (e < EE) atomicAdd(&g_cnt[dst[e]], 1);
}

// single block, 1024 threads: exclusive scan of counts -> offs,
// also deg^{-1/2}, deg^{-1}, and re-zero counts (cursor for scatter).
__global__ void k_scan() {
    __shared__ int ssum[1024];
    int t = threadIdx.x;
    const int CH = (NN + 1023) / 1024;   // 49
    int lo = t * CH;
    int hi = lo + CH; if (hi > NN) hi = NN;
    if (lo > NN) lo = NN;
    int s = 0;
    for (int i = lo; i < hi; i++) s += g_cnt[i];
    ssum[t] = s;
    __syncthreads();
    for (int off = 1; off < 1024; off <<= 1) {
        int v = (t >= off) ? ssum[t - off] : 0;
        __syncthreads();
        ssum[t] += v;
        __syncthreads();
    }
    int base = (t > 0) ? ssum[t - 1] : 0;
    for (int i = lo; i < hi; i++) {
        int c = g_cnt[i];
        g_offs[i] = base;
        base += c;
        float deg = (float)(c + 1);
        g_isqrt[i] = 1.0f / sqrtf(deg);
        g_dinv[i]  = 1.0f / deg;
        g_cnt[i]   = 0;
    }
    if (t == 1023) g_offs[NN] = ssum[1023];
}

__global__ void k_scatter(const int* __restrict__ src, const int* __restrict__ dst) {
    int e = blockIdx.x * blockDim.x + threadIdx.x;
    if (e < EE) {
        int d = dst[e];
        int pos = g_offs[d] + atomicAdd(&g_cnt[d], 1);
        g_csr[pos] = src[e];
    }
}

// ---------------- EmbeddingBag(sum, weighted) + L2 normalize -----------------
// one warp per node; lane owns 4 contiguous columns (float4)
__global__ void k_embed(const int* __restrict__ fidx, const int* __restrict__ foff,
                        const float* __restrict__ fw, const float* __restrict__ emb) {
    int w = (blockIdx.x * blockDim.x + threadIdx.x) >> 5;
    int lane = threadIdx.x & 31;
    if (w >= NN) return;
    int start = foff[w];
    int end = (w + 1 < NN) ? foff[w + 1] : TOT;
    float4 acc = make_float4(0.f, 0.f, 0.f, 0.f);
    #pragma unroll 4
    for (int k = start; k < end; k++) {
        int idx = fidx[k];
        float wt = fw[k];
        float4 v = ((const float4*)emb)[idx * 32 + lane];
        acc.x = fmaf(wt, v.x, acc.x);
        acc.y = fmaf(wt, v.y, acc.y);
        acc.z = fmaf(wt, v.z, acc.z);
        acc.w = fmaf(wt, v.w, acc.w);
    }
    float ss = acc.x * acc.x + acc.y * acc.y + acc.z * acc.z + acc.w * acc.w;
    for (int o = 16; o > 0; o >>= 1) ss += __shfl_xor_sync(0xffffffffu, ss, o);
    float inv = 1.0f / fmaxf(sqrtf(ss), 1e-12f);
    float4 r = make_float4(acc.x * inv, acc.y * inv, acc.z * inv, acc.w * inv);
    ((float4*)g_x)[w * 32 + lane] = r;
}

// ---------------- GCN aggregation: out = isqrt_i * sum_j isqrt_j*in_j + dinv_i*in_i
// one warp per node, CSR gather, 4-way unrolled for MLP
__global__ void k_agg(const float* __restrict__ in, float* __restrict__ out) {
    int w = (blockIdx.x * blockDim.x + threadIdx.x) >> 5;
    int lane = threadIdx.x & 31;
    if (w >= NN) return;
    int lo = g_offs[w], hi = g_offs[w + 1];
    const float4* in4 = (const float4*)in;
    float4 acc = make_float4(0.f, 0.f, 0.f, 0.f);
    int p = lo;
    for (; p + 4 <= hi; p += 4) {
        int j0 = g_csr[p], j1 = g_csr[p + 1], j2 = g_csr[p + 2], j3 = g_csr[p + 3];
        float w0 = g_isqrt[j0], w1 = g_isqrt[j1], w2 = g_isqrt[j2], w3 = g_isqrt[j3];
        float4 v0 = in4[j0 * 32 + lane];
        float4 v1 = in4[j1 * 32 + lane];
        float4 v2 = in4[j2 * 32 + lane];
        float4 v3 = in4[j3 * 32 + lane];
        acc.x = fmaf(w0, v0.x, fmaf(w1, v1.x, fmaf(w2, v2.x, fmaf(w3, v3.x, acc.x))));
        acc.y = fmaf(w0, v0.y, fmaf(w1, v1.y, fmaf(w2, v2.y, fmaf(w3, v3.y, acc.y))));
        acc.z = fmaf(w0, v0.z, fmaf(w1, v1.z, fmaf(w2, v2.z, fmaf(w3, v3.z, acc.z))));
        acc.w = fmaf(w0, v0.w, fmaf(w1, v1.w, fmaf(w2, v2.w, fmaf(w3, v3.w, acc.w))));
    }
    for (; p < hi; p++) {
        int j = g_csr[p];
        float wj = g_isqrt[j];
        float4 v = in4[j * 32 + lane];
        acc.x = fmaf(wj, v.x, acc.x);
        acc.y = fmaf(wj, v.y, acc.y);
        acc.z = fmaf(wj, v.z, acc.z);
        acc.w = fmaf(wj, v.w, acc.w);
    }
    float si = g_isqrt[w], di = g_dinv[w];
    float4 self = in4[w * 32 + lane];
    float4 o;
    o.x = acc.x * si + self.x * di;
    o.y = acc.y * si + self.y * di;
    o.z = acc.z * si + self.z * di;
    o.w = acc.w * si + self.w * di;
    ((float4*)out)[w * 32 + lane] = o;
}

// ---------------- GEMM1: h = relu(P @ W1 + b1)   (N x 128 @ 128 x 128) -------
// 256 threads, 32 rows/block, 2x8 register tile, K tiled by 64 through smem
__global__ __launch_bounds__(256) void k_gemm1(const float* __restrict__ P,
                                               const float* __restrict__ W,
                                               const float* __restrict__ b,
                                               float* __restrict__ out) {
    __shared__ float sW[64][128];
    __shared__ float sP[32][65];
    int t = threadIdx.x;
    int row0 = blockIdx.x * 32;
    int tr = t >> 4, tc = t & 15;
    float acc[2][8];
    #pragma unroll
    for (int i = 0; i < 2; i++)
        #pragma unroll
        for (int j = 0; j < 8; j++) acc[i][j] = 0.f;

    for (int c = 0; c < 2; c++) {
        #pragma unroll
        for (int k = 0; k < 32; k++) {
            int e = t + k * 256;
            sW[e >> 7][e & 127] = W[c * 8192 + e];
        }
        #pragma unroll
        for (int k = 0; k < 8; k++) {
            int e = t + k * 256;
            int r = e >> 6, d = e & 63;
            int gr = row0 + r;
            sP[r][d] = (gr < NN) ? P[gr * 128 + c * 64 + d] : 0.f;
        }
        __syncthreads();
        #pragma unroll 8
        for (int d = 0; d < 64; d++) {
            float a0 = sP[2 * tr][d], a1 = sP[2 * tr + 1][d];
            float4 w0 = *(const float4*)&sW[d][tc * 8];
            float4 w1 = *(const float4*)&sW[d][tc * 8 + 4];
            acc[0][0] = fmaf(a0, w0.x, acc[0][0]);
            acc[0][1] = fmaf(a0, w0.y, acc[0][1]);
            acc[0][2] = fmaf(a0, w0.z, acc[0][2]);
            acc[0][3] = fmaf(a0, w0.w, acc[0][3]);
            acc[0][4] = fmaf(a0, w1.x, acc[0][4]);
            acc[0][5] = fmaf(a0, w1.y, acc[0][5]);
            acc[0][6] = fmaf(a0, w1.z, acc[0][6]);
            acc[0][7] = fmaf(a0, w1.w, acc[0][7]);
            acc[1][0] = fmaf(a1, w0.x, acc[1][0]);
            acc[1][1] = fmaf(a1, w0.y, acc[1][1]);
            acc[1][2] = fmaf(a1, w0.z, acc[1][2]);
            acc[1][3] = fmaf(a1, w0.w, acc[1][3]);
            acc[1][4] = fmaf(a1, w1.x, acc[1][4]);
            acc[1][5] = fmaf(a1, w1.y, acc[1][5]);
            acc[1][6] = fmaf(a1, w1.z, acc[1][6]);
            acc[1][7] = fmaf(a1, w1.w, acc[1][7]);
        }
        __syncthreads();
    }
    #pragma unroll
    for (int rr = 0; rr < 2; rr++) {
        int gr = row0 + 2 * tr + rr;
        if (gr < NN) {
            #pragma unroll
            for (int cc = 0; cc < 8; cc++) {
                int col = tc * 8 + cc;
                out[gr * 128 + col] = fmaxf(acc[rr][cc] + b[col], 0.f);
            }
        }
    }
}

// ---------------- GEMM2: [mu | ls] = P @ [Wmu | Wls] + [bmu | bls] -----------
__global__ __launch_bounds__(256) void k_gemm2(const float* __restrict__ P,
                                               const float* __restrict__ Wa,
                                               const float* __restrict__ Wb,
                                               const float* __restrict__ ba,
                                               const float* __restrict__ bb,
                                               float* __restrict__ out) {
    __shared__ float sW[64][128];
    __shared__ float sP[32][65];
    int t = threadIdx.x;
    int row0 = blockIdx.x * 32;
    int tr = t >> 4, tc = t & 15;
    float acc[2][8];
    #pragma unroll
    for (int i = 0; i < 2; i++)
        #pragma unroll
        for (int j = 0; j < 8; j++) acc[i][j] = 0.f;

    for (int c = 0; c < 2; c++) {
        #pragma unroll
        for (int k = 0; k < 32; k++) {
            int e = t + k * 256;
            int dd = e >> 7, col = e & 127;
            int gd = c * 64 + dd;
            sW[dd][col] = (col < 64) ? Wa[gd * 64 + col] : Wb[gd * 64 + (col - 64)];
        }
        #pragma unroll
        for (int k = 0; k < 8; k++) {
            int e = t + k * 256;
            int r = e >> 6, d = e & 63;
            int gr = row0 + r;
            sP[r][d] = (gr < NN) ? P[gr * 128 + c * 64 + d] : 0.f;
        }
        __syncthreads();
        #pragma unroll 8
        for (int d = 0; d < 64; d++) {
            float a0 = sP[2 * tr][d], a1 = sP[2 * tr + 1][d];
            float4 w0 = *(const float4*)&sW[d][tc * 8];
            float4 w1 = *(const float4*)&sW[d][tc * 8 + 4];
            acc[0][0] = fmaf(a0, w0.x, acc[0][0]);
            acc[0][1] = fmaf(a0, w0.y, acc[0][1]);
            acc[0][2] = fmaf(a0, w0.z, acc[0][2]);
            acc[0][3] = fmaf(a0, w0.w, acc[0][3]);
            acc[0][4] = fmaf(a0, w1.x, acc[0][4]);
            acc[0][5] = fmaf(a0, w1.y, acc[0][5]);
            acc[0][6] = fmaf(a0, w1.z, acc[0][6]);
            acc[0][7] = fmaf(a0, w1.w, acc[0][7]);
            acc[1][0] = fmaf(a1, w0.x, acc[1][0]);
            acc[1][1] = fmaf(a1, w0.y, acc[1][1]);
            acc[1][2] = fmaf(a1, w0.z, acc[1][2]);
            acc[1][3] = fmaf(a1, w0.w, acc[1][3]);
            acc[1][4] = fmaf(a1, w1.x, acc[1][4]);
            acc[1][5] = fmaf(a1, w1.y, acc[1][5]);
            acc[1][6] = fmaf(a1, w1.z, acc[1][6]);
            acc[1][7] = fmaf(a1, w1.w, acc[1][7]);
        }
        __syncthreads();
    }
    #pragma unroll
    for (int rr = 0; rr < 2; rr++) {
        int gr = row0 + 2 * tr + rr;
        if (gr < NN) {
            #pragma unroll
            for (int cc = 0; cc < 8; cc++) {
                int col = tc * 8 + cc;
                float bias = (col < 64) ? ba[col] : bb[col - 64];
                out[gr * 128 + col] = acc[rr][cc] + bias;
            }
        }
    }
}

// ---------------- z = mu + noise * exp(logstd) --------------------------------
__global__ void k_z(const float* __restrict__ ms, const float* __restrict__ noise) {
    int i = blockIdx.x * blockDim.x + threadIdx.x;
    if (i >= NN * OO) return;
    int r = i >> 6, o = i & 63;
    float mu = ms[r * 128 + o];
    float ls = ms[r * 128 + 64 + o];
    g_z[i] = fmaf(noise[i], expf(ls), mu);
}

// ---------------- decoder: logits[e] = dot(z[src], z[dst]) over 64 ------------
// half-warp (16 lanes x float4) per edge
__global__ void k_dec(const int* __restrict__ src, const int* __restrict__ dst,
                      float* __restrict__ out) {
    int g = blockIdx.x * (blockDim.x >> 4) + (threadIdx.x >> 4);
    int l = threadIdx.x & 15;
    if (g >= EE) return;
    int s = src[g], d = dst[g];
    float4 a = ((const float4*)g_z)[s * 16 + l];
    float4 b = ((const float4*)g_z)[d * 16 + l];
    float v = a.x * b.x + a.y * b.y + a.z * b.z + a.w * b.w;
    v += __shfl_xor_sync(0xffffffffu, v, 8);
    v += __shfl_xor_sync(0xffffffffu, v, 4);
    v += __shfl_xor_sync(0xffffffffu, v, 2);
    v += __shfl_xor_sync(0xffffffffu, v, 1);
    if (l == 0) out[g] = v;
}

// ---------------- launch -------------------------------------------------------
extern "C" void kernel_launch(void* const* d_in, const int* in_sizes, int n_in,
                              void* d_out, int out_size) {
    const int*   fidx  = (const int*)d_in[0];
    const int*   foff  = (const int*)d_in[1];
    const float* fw    = (const float*)d_in[2];
    const int*   edge  = (const int*)d_in[3];
    const float* noise = (const float*)d_in[4];
    const float* emb   = (const float*)d_in[5];
    const float* W1    = (const float*)d_in[6];
    const float* b1    = (const float*)d_in[7];
    const float* Wmu   = (const float*)d_in[8];
    const float* bmu   = (const float*)d_in[9];
    const float* Wls   = (const float*)d_in[10];
    const float* bls   = (const float*)d_in[11];
    float* out = (float*)d_out;

    const int* src = edge;
    const int* dst = edge + EE;

    float *px = nullptr, *pp = nullptr, *ph = nullptr;
    cudaGetSymbolAddress((void**)&px, g_x);
    cudaGetSymbolAddress((void**)&pp, g_p);
    cudaGetSymbolAddress((void**)&ph, g_h);

    k_zero_cnt<<<(NN + 255) / 256, 256>>>();
    k_hist<<<(EE + 255) / 256, 256>>>(dst);
    k_scan<<<1, 1024>>>();
    k_scatter<<<(EE + 255) / 256, 256>>>(src, dst);

    k_embed<<<(NN + 3) / 4, 128>>>(fidx, foff, fw, emb);

    k_agg<<<(NN + 3) / 4, 128>>>(px, pp);                       // p1 = A~ x
    k_gemm1<<<(NN + 31) / 32, 256>>>(pp, W1, b1, ph);           // h = relu(p1 W1 + b1)
    k_agg<<<(NN + 3) / 4, 128>>>(ph, pp);                       // p2 = A~ h
    k_gemm2<<<(NN + 31) / 32, 256>>>(pp, Wmu, Wls, bmu, bls, px); // [mu|ls]
    k_z<<<(NN * OO + 255) / 256, 256>>>(px, noise);
    k_dec<<<(EE + 15) / 16, 256>>>(src, dst, out);
}

// round 2
// speedup vs baseline: 1.2534x; 1.2534x over previous
#include <cuda_runtime.h>
#include <math.h>

#define NN 50000
#define EE 1600000
#define VV 100000
#define DD 128
#define OO 64
#define TOT (NN*16)
#define NB 49   // ceil(NN/1024)

// ---------------- scratch (static device globals; no allocs allowed) ----------
__device__ int   g_cnt[NN];
__device__ int   g_offs[NN + 1];
__device__ int   g_csr[EE];
__device__ int   g_bsum[64];
__device__ int   g_bpre[64];
__device__ float g_isqrt[NN];
__device__ float g_dinv[NN];
__device__ float g_x[NN * DD];   // embedding output
__device__ float g_p[NN * DD];   // aggregation output (p1, then p2)
__device__ float g_h[NN * DD];   // relu(gemm1)
__device__ float g_z[NN * OO];

// ---------------- CSR build ---------------------------------------------------
__global__ void k_hist(const int* __restrict__ dst) {
    int base = (blockIdx.x * blockDim.x + threadIdx.x) * 4;
    if (base + 4 <= EE) {
        int4 d = *(const int4*)(dst + base);
        atomicAdd(&g_cnt[d.x], 1);
        atomicAdd(&g_cnt[d.y], 1);
        atomicAdd(&g_cnt[d.z], 1);
        atomicAdd(&g_cnt[d.w], 1);
    } else {
        for (int e = base; e < EE; e++) atomicAdd(&g_cnt[dst[e]], 1);
    }
}

// level-1 scan: each 1024-block exclusive-scans its chunk, writes block total
__global__ __launch_bounds__(1024) void k_scan1() {
    __shared__ int s[1024];
    int t = threadIdx.x;
    int i = blockIdx.x * 1024 + t;
    int v = (i < NN) ? g_cnt[i] : 0;
    s[t] = v;
    __syncthreads();
    #pragma unroll
    for (int off = 1; off < 1024; off <<= 1) {
        int u = (t >= off) ? s[t - off] : 0;
        __syncthreads();
        s[t] += u;
        __syncthreads();
    }
    if (i < NN) g_offs[i] = s[t] - v;        // local exclusive
    if (t == 1023) g_bsum[blockIdx.x] = s[1023];
}

// level-2 scan of 49 block sums (single tiny block)
__global__ void k_scan2() {
    __shared__ int s[64];
    int t = threadIdx.x;
    int v = (t < NB) ? g_bsum[t] : 0;
    s[t] = v;
    __syncthreads();
    #pragma unroll
    for (int off = 1; off < 64; off <<= 1) {
        int u = (t >= off) ? s[t - off] : 0;
        __syncthreads();
        s[t] += u;
        __syncthreads();
    }
    g_bpre[t] = s[t] - v;
}

// fixup + degree math (grid-wide, so MUFU is parallel) + re-zero counters
__global__ void k_scan3() {
    int i = blockIdx.x * blockDim.x + threadIdx.x;
    if (i >= NN) return;
    g_offs[i] += g_bpre[i >> 10];
    int c = g_cnt[i];
    float deg = (float)(c + 1);
    g_isqrt[i] = rsqrtf(deg);
    g_dinv[i]  = 1.0f / deg;
    g_cnt[i]   = 0;
    if (i == 0) g_offs[NN] = EE;
}

__global__ void k_scatter(const int* __restrict__ src, const int* __restrict__ dst) {
    int base = (blockIdx.x * blockDim.x + threadIdx.x) * 4;
    if (base + 4 <= EE) {
        int4 d = *(const int4*)(dst + base);
        int4 s = *(const int4*)(src + base);
        int p0 = g_offs[d.x] + atomicAdd(&g_cnt[d.x], 1); g_csr[p0] = s.x;
        int p1 = g_offs[d.y] + atomicAdd(&g_cnt[d.y], 1); g_csr[p1] = s.y;
        int p2 = g_offs[d.z] + atomicAdd(&g_cnt[d.z], 1); g_csr[p2] = s.z;
        int p3 = g_offs[d.w] + atomicAdd(&g_cnt[d.w], 1); g_csr[p3] = s.w;
    } else {
        for (int e = base; e < EE; e++) {
            int d = dst[e];
            int pos = g_offs[d] + atomicAdd(&g_cnt[d], 1);
            g_csr[pos] = src[e];
        }
    }
}

// ---------------- EmbeddingBag(sum, weighted) + L2 normalize -----------------
__global__ void k_embed(const int* __restrict__ fidx, const int* __restrict__ foff,
                        const float* __restrict__ fw, const float* __restrict__ emb) {
    int w = (blockIdx.x * blockDim.x + threadIdx.x) >> 5;
    int lane = threadIdx.x & 31;
    if (w >= NN) return;
    int start = foff[w];
    int end = (w + 1 < NN) ? foff[w + 1] : TOT;
    float4 acc = make_float4(0.f, 0.f, 0.f, 0.f);
    int k = start;
    for (; k + 4 <= end; k += 4) {
        int i0 = fidx[k], i1 = fidx[k+1], i2 = fidx[k+2], i3 = fidx[k+3];
        float w0 = fw[k], w1 = fw[k+1], w2 = fw[k+2], w3 = fw[k+3];
        float4 v0 = ((const float4*)emb)[i0 * 32 + lane];
        float4 v1 = ((const float4*)emb)[i1 * 32 + lane];
        float4 v2 = ((const float4*)emb)[i2 * 32 + lane];
        float4 v3 = ((const float4*)emb)[i3 * 32 + lane];
        acc.x = fmaf(w0, v0.x, fmaf(w1, v1.x, fmaf(w2, v2.x, fmaf(w3, v3.x, acc.x))));
        acc.y = fmaf(w0, v0.y, fmaf(w1, v1.y, fmaf(w2, v2.y, fmaf(w3, v3.y, acc.y))));
        acc.z = fmaf(w0, v0.z, fmaf(w1, v1.z, fmaf(w2, v2.z, fmaf(w3, v3.z, acc.z))));
        acc.w = fmaf(w0, v0.w, fmaf(w1, v1.w, fmaf(w2, v2.w, fmaf(w3, v3.w, acc.w))));
    }
    for (; k < end; k++) {
        int idx = fidx[k];
        float wt = fw[k];
        float4 v = ((const float4*)emb)[idx * 32 + lane];
        acc.x = fmaf(wt, v.x, acc.x);
        acc.y = fmaf(wt, v.y, acc.y);
        acc.z = fmaf(wt, v.z, acc.z);
        acc.w = fmaf(wt, v.w, acc.w);
    }
    float ss = acc.x * acc.x + acc.y * acc.y + acc.z * acc.z + acc.w * acc.w;
    for (int o = 16; o > 0; o >>= 1) ss += __shfl_xor_sync(0xffffffffu, ss, o);
    float inv = 1.0f / fmaxf(sqrtf(ss), 1e-12f);
    float4 r = make_float4(acc.x * inv, acc.y * inv, acc.z * inv, acc.w * inv);
    ((float4*)g_x)[w * 32 + lane] = r;
}

// ---------------- GCN aggregation ---------------------------------------------
__global__ void k_agg(const float* __restrict__ in, float* __restrict__ out) {
    int w = (blockIdx.x * blockDim.x + threadIdx.x) >> 5;
    int lane = threadIdx.x & 31;
    if (w >= NN) return;
    int lo = g_offs[w], hi = g_offs[w + 1];
    const float4* in4 = (const float4*)in;
    float4 acc = make_float4(0.f, 0.f, 0.f, 0.f);
    int p = lo;
    for (; p + 8 <= hi; p += 8) {
        int j[8];
        float wj[8];
        #pragma unroll
        for (int q = 0; q < 8; q++) j[q] = g_csr[p + q];
        #pragma unroll
        for (int q = 0; q < 8; q++) wj[q] = g_isqrt[j[q]];
        float4 v[8];
        #pragma unroll
        for (int q = 0; q < 8; q++) v[q] = in4[j[q] * 32 + lane];
        #pragma unroll
        for (int q = 0; q < 8; q++) {
            acc.x = fmaf(wj[q], v[q].x, acc.x);
            acc.y = fmaf(wj[q], v[q].y, acc.y);
            acc.z = fmaf(wj[q], v[q].z, acc.z);
            acc.w = fmaf(wj[q], v[q].w, acc.w);
        }
    }
    for (; p < hi; p++) {
        int jj = g_csr[p];
        float wj = g_isqrt[jj];
        float4 v = in4[jj * 32 + lane];
        acc.x = fmaf(wj, v.x, acc.x);
        acc.y = fmaf(wj, v.y, acc.y);
        acc.z = fmaf(wj, v.z, acc.z);
        acc.w = fmaf(wj, v.w, acc.w);
    }
    float si = g_isqrt[w], di = g_dinv[w];
    float4 self = in4[w * 32 + lane];
    float4 o;
    o.x = acc.x * si + self.x * di;
    o.y = acc.y * si + self.y * di;
    o.z = acc.z * si + self.z * di;
    o.w = acc.w * si + self.w * di;
    ((float4*)out)[w * 32 + lane] = o;
}

// ---------------- GEMM1: h = relu(P @ W1 + b1) ---------------------------------
__global__ __launch_bounds__(256) void k_gemm1(const float* __restrict__ P,
                                               const float* __restrict__ W,
                                               const float* __restrict__ b,
                                               float* __restrict__ out) {
    __shared__ float sW[64][128];
    __shared__ float sP[32][65];
    int t = threadIdx.x;
    int row0 = blockIdx.x * 32;
    int tr = t >> 4, tc = t & 15;
    float acc[2][8];
    #pragma unroll
    for (int i = 0; i < 2; i++)
        #pragma unroll
        for (int j = 0; j < 8; j++) acc[i][j] = 0.f;

    for (int c = 0; c < 2; c++) {
        #pragma unroll
        for (int k = 0; k < 32; k++) {
            int e = t + k * 256;
            sW[e >> 7][e & 127] = W[c * 8192 + e];
        }
        #pragma unroll
        for (int k = 0; k < 8; k++) {
            int e = t + k * 256;
            int r = e >> 6, d = e & 63;
            int gr = row0 + r;
            sP[r][d] = (gr < NN) ? P[gr * 128 + c * 64 + d] : 0.f;
        }
        __syncthreads();
        #pragma unroll 8
        for (int d = 0; d < 64; d++) {
            float a0 = sP[2 * tr][d], a1 = sP[2 * tr + 1][d];
            float4 w0 = *(const float4*)&sW[d][tc * 8];
            float4 w1 = *(const float4*)&sW[d][tc * 8 + 4];
            acc[0][0] = fmaf(a0, w0.x, acc[0][0]);
            acc[0][1] = fmaf(a0, w0.y, acc[0][1]);
            acc[0][2] = fmaf(a0, w0.z, acc[0][2]);
            acc[0][3] = fmaf(a0, w0.w, acc[0][3]);
            acc[0][4] = fmaf(a0, w1.x, acc[0][4]);
            acc[0][5] = fmaf(a0, w1.y, acc[0][5]);
            acc[0][6] = fmaf(a0, w1.z, acc[0][6]);
            acc[0][7] = fmaf(a0, w1.w, acc[0][7]);
            acc[1][0] = fmaf(a1, w0.x, acc[1][0]);
            acc[1][1] = fmaf(a1, w0.y, acc[1][1]);
            acc[1][2] = fmaf(a1, w0.z, acc[1][2]);
            acc[1][3] = fmaf(a1, w0.w, acc[1][3]);
            acc[1][4] = fmaf(a1, w1.x, acc[1][4]);
            acc[1][5] = fmaf(a1, w1.y, acc[1][5]);
            acc[1][6] = fmaf(a1, w1.z, acc[1][6]);
            acc[1][7] = fmaf(a1, w1.w, acc[1][7]);
        }
        __syncthreads();
    }
    #pragma unroll
    for (int rr = 0; rr < 2; rr++) {
        int gr = row0 + 2 * tr + rr;
        if (gr < NN) {
            #pragma unroll
            for (int cc = 0; cc < 8; cc++) {
                int col = tc * 8 + cc;
                out[gr * 128 + col] = fmaxf(acc[rr][cc] + b[col], 0.f);
            }
        }
    }
}

// ---------------- GEMM2 + fused z: z = (P@Wmu+bmu) + noise*exp(P@Wls+bls) -----
__global__ __launch_bounds__(256) void k_gemm2z(const float* __restrict__ P,
                                                const float* __restrict__ Wa,
                                                const float* __restrict__ Wb,
                                                const float* __restrict__ ba,
                                                const float* __restrict__ bb,
                                                const float* __restrict__ noise) {
    __shared__ float sW[64][128];
    __shared__ float sP[32][65];
    __shared__ float sbuf[32][65];
    int t = threadIdx.x;
    int row0 = blockIdx.x * 32;
    int tr = t >> 4, tc = t & 15;
    float acc[2][8];
    #pragma unroll
    for (int i = 0; i < 2; i++)
        #pragma unroll
        for (int j = 0; j < 8; j++) acc[i][j] = 0.f;

    for (int c = 0; c < 2; c++) {
        #pragma unroll
        for (int k = 0; k < 32; k++) {
            int e = t + k * 256;
            int dd = e >> 7, col = e & 127;
            int gd = c * 64 + dd;
            sW[dd][col] = (col < 64) ? Wa[gd * 64 + col] : Wb[gd * 64 + (col - 64)];
        }
        #pragma unroll
        for (int k = 0; k < 8; k++) {
            int e = t + k * 256;
            int r = e >> 6, d = e & 63;
            int gr = row0 + r;
            sP[r][d] = (gr < NN) ? P[gr * 128 + c * 64 + d] : 0.f;
        }
        __syncthreads();
        #pragma unroll 8
        for (int d = 0; d < 64; d++) {
            float a0 = sP[2 * tr][d], a1 = sP[2 * tr + 1][d];
            float4 w0 = *(const float4*)&sW[d][tc * 8];
            float4 w1 = *(const float4*)&sW[d][tc * 8 + 4];
            acc[0][0] = fmaf(a0, w0.x, acc[0][0]);
            acc[0][1] = fmaf(a0, w0.y, acc[0][1]);
            acc[0][2] = fmaf(a0, w0.z, acc[0][2]);
            acc[0][3] = fmaf(a0, w0.w, acc[0][3]);
            acc[0][4] = fmaf(a0, w1.x, acc[0][4]);
            acc[0][5] = fmaf(a0, w1.y, acc[0][5]);
            acc[0][6] = fmaf(a0, w1.z, acc[0][6]);
            acc[0][7] = fmaf(a0, w1.w, acc[0][7]);
            acc[1][0] = fmaf(a1, w0.x, acc[1][0]);
            acc[1][1] = fmaf(a1, w0.y, acc[1][1]);
            acc[1][2] = fmaf(a1, w0.z, acc[1][2]);
            acc[1][3] = fmaf(a1, w0.w, acc[1][3]);
            acc[1][4] = fmaf(a1, w1.x, acc[1][4]);
            acc[1][5] = fmaf(a1, w1.y, acc[1][5]);
            acc[1][6] = fmaf(a1, w1.z, acc[1][6]);
            acc[1][7] = fmaf(a1, w1.w, acc[1][7]);
        }
        __syncthreads();
    }

    // ls half: compute noise * exp(ls) into sbuf
    if (tc >= 8) {
        #pragma unroll
        for (int rr = 0; rr < 2; rr++) {
            int gr = row0 + 2 * tr + rr;
            if (gr < NN) {
                #pragma unroll
                for (int cc = 0; cc < 8; cc++) {
                    int o = (tc - 8) * 8 + cc;
                    float ls = acc[rr][cc] + bb[o];
                    sbuf[2 * tr + rr][o] = expf(ls) * noise[gr * 64 + o];
                }
            }
        }
    }
    __syncthreads();
    // mu half: z = mu + sbuf
    if (tc < 8) {
        #pragma unroll
        for (int rr = 0; rr < 2; rr++) {
            int gr = row0 + 2 * tr + rr;
            if (gr < NN) {
                #pragma unroll
                for (int cc = 0; cc < 8; cc++) {
                    int o = tc * 8 + cc;
                    g_z[gr * 64 + o] = acc[rr][cc] + ba[o] + sbuf[2 * tr + rr][o];
                }
            }
        }
    }
}

// ---------------- decoder: logits[e] = dot(z[src], z[dst]) --------------------
__global__ void k_dec(const int* __restrict__ src, const int* __restrict__ dst,
                      float* __restrict__ out) {
    int g = blockIdx.x * (blockDim.x >> 4) + (threadIdx.x >> 4);
    int l = threadIdx.x & 15;
    if (g >= EE) return;
    int s = src[g], d = dst[g];
    float4 a = ((const float4*)g_z)[s * 16 + l];
    float4 b = ((const float4*)g_z)[d * 16 + l];
    float v = a.x * b.x + a.y * b.y + a.z * b.z + a.w * b.w;
    v += __shfl_xor_sync(0xffffffffu, v, 8);
    v += __shfl_xor_sync(0xffffffffu, v, 4);
    v += __shfl_xor_sync(0xffffffffu, v, 2);
    v += __shfl_xor_sync(0xffffffffu, v, 1);
    if (l == 0) out[g] = v;
}

// ---------------- launch -------------------------------------------------------
extern "C" void kernel_launch(void* const* d_in, const int* in_sizes, int n_in,
                              void* d_out, int out_size) {
    const int*   fidx  = (const int*)d_in[0];
    const int*   foff  = (const int*)d_in[1];
    const float* fw    = (const float*)d_in[2];
    const int*   edge  = (const int*)d_in[3];
    const float* noise = (const float*)d_in[4];
    const float* emb   = (const float*)d_in[5];
    const float* W1    = (const float*)d_in[6];
    const float* b1    = (const float*)d_in[7];
    const float* Wmu   = (const float*)d_in[8];
    const float* bmu   = (const float*)d_in[9];
    const float* Wls   = (const float*)d_in[10];
    const float* bls   = (const float*)d_in[11];
    float* out = (float*)d_out;

    const int* src = edge;
    const int* dst = edge + EE;

    float *px = nullptr, *pp = nullptr, *ph = nullptr;
    int* pcnt = nullptr;
    cudaGetSymbolAddress((void**)&px, g_x);
    cudaGetSymbolAddress((void**)&pp, g_p);
    cudaGetSymbolAddress((void**)&ph, g_h);
    cudaGetSymbolAddress((void**)&pcnt, g_cnt);

    cudaMemsetAsync(pcnt, 0, NN * sizeof(int));
    k_hist<<<(EE / 4 + 255) / 256, 256>>>(dst);
    k_scan1<<<NB, 1024>>>();
    k_scan2<<<1, 64>>>();
    k_scan3<<<(NN + 255) / 256, 256>>>();
    k_scatter<<<(EE / 4 + 255) / 256, 256>>>(src, dst);

    k_embed<<<(NN + 3) / 4, 128>>>(fidx, foff, fw, emb);

    k_agg<<<(NN + 3) / 4, 128>>>(px, pp);                         // p1 = A~ x
    k_gemm1<<<(NN + 31) / 32, 256>>>(pp, W1, b1, ph);             // h = relu(p1 W1 + b1)
    k_agg<<<(NN + 3) / 4, 128>>>(ph, pp);                         // p2 = A~ h
    k_gemm2z<<<(NN + 31) / 32, 256>>>(pp, Wmu, Wls, bmu, bls, noise); // z fused
    k_dec<<<(EE + 15) / 16, 256>>>(src, dst, out);
}

// round 3
// speedup vs baseline: 1.7502x; 1.3964x over previous
#include <cuda_runtime.h>
#include <math.h>

#define NN 50000
#define EE 1600000
#define VV 100000
#define DD 128
#define OO 64
#define TOT (NN*16)
#define NB 49   // ceil(NN/1024)

// ---------------- scratch (static device globals; no allocs allowed) ----------
__device__ int   g_cnt[NN];
__device__ int   g_offs[NN + 1];
__device__ int   g_csr[EE];
__device__ int   g_bsum[64];
__device__ int   g_bpre[64];
__device__ float g_isqrt[NN];
__device__ float g_dinv[NN];
__device__ float g_x[NN * DD];   // embedding output
__device__ float g_p[NN * DD];   // aggregation output (p1, then p2)
__device__ float g_h[NN * DD];   // relu(gemm1)
__device__ float g_z[NN * OO];

// ---------------- CSR build ---------------------------------------------------
__global__ void k_hist(const int* __restrict__ dst) {
    int base = (blockIdx.x * blockDim.x + threadIdx.x) * 4;
    if (base + 4 <= EE) {
        int4 d = *(const int4*)(dst + base);
        atomicAdd(&g_cnt[d.x], 1);
        atomicAdd(&g_cnt[d.y], 1);
        atomicAdd(&g_cnt[d.z], 1);
        atomicAdd(&g_cnt[d.w], 1);
    } else {
        for (int e = base; e < EE; e++) atomicAdd(&g_cnt[dst[e]], 1);
    }
}

__global__ __launch_bounds__(1024) void k_scan1() {
    __shared__ int s[1024];
    int t = threadIdx.x;
    int i = blockIdx.x * 1024 + t;
    int v = (i < NN) ? g_cnt[i] : 0;
    s[t] = v;
    __syncthreads();
    #pragma unroll
    for (int off = 1; off < 1024; off <<= 1) {
        int u = (t >= off) ? s[t - off] : 0;
        __syncthreads();
        s[t] += u;
        __syncthreads();
    }
    if (i < NN) g_offs[i] = s[t] - v;
    if (t == 1023) g_bsum[blockIdx.x] = s[1023];
}

__global__ void k_scan2() {
    __shared__ int s[64];
    int t = threadIdx.x;
    int v = (t < NB) ? g_bsum[t] : 0;
    s[t] = v;
    __syncthreads();
    #pragma unroll
    for (int off = 1; off < 64; off <<= 1) {
        int u = (t >= off) ? s[t - off] : 0;
        __syncthreads();
        s[t] += u;
        __syncthreads();
    }
    g_bpre[t] = s[t] - v;
}

__global__ void k_scan3() {
    int i = blockIdx.x * blockDim.x + threadIdx.x;
    if (i >= NN) return;
    g_offs[i] += g_bpre[i >> 10];
    int c = g_cnt[i];
    float deg = (float)(c + 1);
    g_isqrt[i] = rsqrtf(deg);
    g_dinv[i]  = 1.0f / deg;
    g_cnt[i]   = 0;
    if (i == 0) g_offs[NN] = EE;
}

__global__ void k_scatter(const int* __restrict__ src, const int* __restrict__ dst) {
    int base = (blockIdx.x * blockDim.x + threadIdx.x) * 4;
    if (base + 4 <= EE) {
        int4 d = *(const int4*)(dst + base);
        int4 s = *(const int4*)(src + base);
        int p0 = g_offs[d.x] + atomicAdd(&g_cnt[d.x], 1); g_csr[p0] = s.x;
        int p1 = g_offs[d.y] + atomicAdd(&g_cnt[d.y], 1); g_csr[p1] = s.y;
        int p2 = g_offs[d.z] + atomicAdd(&g_cnt[d.z], 1); g_csr[p2] = s.z;
        int p3 = g_offs[d.w] + atomicAdd(&g_cnt[d.w], 1); g_csr[p3] = s.w;
    } else {
        for (int e = base; e < EE; e++) {
            int d = dst[e];
            int pos = g_offs[d] + atomicAdd(&g_cnt[d], 1);
            g_csr[pos] = src[e];
        }
    }
}

// ---------------- EmbeddingBag(sum, weighted) + L2 normalize -----------------
__global__ void k_embed(const int* __restrict__ fidx, const int* __restrict__ foff,
                        const float* __restrict__ fw, const float* __restrict__ emb) {
    int w = (blockIdx.x * blockDim.x + threadIdx.x) >> 5;
    int lane = threadIdx.x & 31;
    if (w >= NN) return;
    int start = foff[w];
    int end = (w + 1 < NN) ? foff[w + 1] : TOT;
    float4 acc = make_float4(0.f, 0.f, 0.f, 0.f);
    int k = start;
    for (; k + 4 <= end; k += 4) {
        int i0 = fidx[k], i1 = fidx[k+1], i2 = fidx[k+2], i3 = fidx[k+3];
        float w0 = fw[k], w1 = fw[k+1], w2 = fw[k+2], w3 = fw[k+3];
        float4 v0 = ((const float4*)emb)[i0 * 32 + lane];
        float4 v1 = ((const float4*)emb)[i1 * 32 + lane];
        float4 v2 = ((const float4*)emb)[i2 * 32 + lane];
        float4 v3 = ((const float4*)emb)[i3 * 32 + lane];
        acc.x = fmaf(w0, v0.x, fmaf(w1, v1.x, fmaf(w2, v2.x, fmaf(w3, v3.x, acc.x))));
        acc.y = fmaf(w0, v0.y, fmaf(w1, v1.y, fmaf(w2, v2.y, fmaf(w3, v3.y, acc.y))));
        acc.z = fmaf(w0, v0.z, fmaf(w1, v1.z, fmaf(w2, v2.z, fmaf(w3, v3.z, acc.z))));
        acc.w = fmaf(w0, v0.w, fmaf(w1, v1.w, fmaf(w2, v2.w, fmaf(w3, v3.w, acc.w))));
    }
    for (; k < end; k++) {
        int idx = fidx[k];
        float wt = fw[k];
        float4 v = ((const float4*)emb)[idx * 32 + lane];
        acc.x = fmaf(wt, v.x, acc.x);
        acc.y = fmaf(wt, v.y, acc.y);
        acc.z = fmaf(wt, v.z, acc.z);
        acc.w = fmaf(wt, v.w, acc.w);
    }
    float ss = acc.x * acc.x + acc.y * acc.y + acc.z * acc.z + acc.w * acc.w;
    for (int o = 16; o > 0; o >>= 1) ss += __shfl_xor_sync(0xffffffffu, ss, o);
    float inv = 1.0f / fmaxf(sqrtf(ss), 1e-12f);
    float4 r = make_float4(acc.x * inv, acc.y * inv, acc.z * inv, acc.w * inv);
    ((float4*)g_x)[w * 32 + lane] = r;
}

// ---------------- GCN aggregation ---------------------------------------------
__global__ void k_agg(const float* __restrict__ in, float* __restrict__ out) {
    int w = (blockIdx.x * blockDim.x + threadIdx.x) >> 5;
    int lane = threadIdx.x & 31;
    if (w >= NN) return;
    int lo = g_offs[w], hi = g_offs[w + 1];
    const float4* in4 = (const float4*)in;
    float4 acc = make_float4(0.f, 0.f, 0.f, 0.f);
    int p = lo;
    for (; p + 8 <= hi; p += 8) {
        int j[8];
        float wj[8];
        #pragma unroll
        for (int q = 0; q < 8; q++) j[q] = g_csr[p + q];
        #pragma unroll
        for (int q = 0; q < 8; q++) wj[q] = g_isqrt[j[q]];
        float4 v[8];
        #pragma unroll
        for (int q = 0; q < 8; q++) v[q] = in4[j[q] * 32 + lane];
        #pragma unroll
        for (int q = 0; q < 8; q++) {
            acc.x = fmaf(wj[q], v[q].x, acc.x);
            acc.y = fmaf(wj[q], v[q].y, acc.y);
            acc.z = fmaf(wj[q], v[q].z, acc.z);
            acc.w = fmaf(wj[q], v[q].w, acc.w);
        }
    }
    for (; p < hi; p++) {
        int jj = g_csr[p];
        float wj = g_isqrt[jj];
        float4 v = in4[jj * 32 + lane];
        acc.x = fmaf(wj, v.x, acc.x);
        acc.y = fmaf(wj, v.y, acc.y);
        acc.z = fmaf(wj, v.z, acc.z);
        acc.w = fmaf(wj, v.w, acc.w);
    }
    float si = g_isqrt[w], di = g_dinv[w];
    float4 self = in4[w * 32 + lane];
    float4 o;
    o.x = acc.x * si + self.x * di;
    o.y = acc.y * si + self.y * di;
    o.z = acc.z * si + self.z * di;
    o.w = acc.w * si + self.w * di;
    ((float4*)out)[w * 32 + lane] = o;
}

// ---------------- GEMM1: h = relu(P @ W1 + b1), 128x128 block, 8x8 thread tile
__global__ __launch_bounds__(256) void k_gemm1(const float* __restrict__ P,
                                               const float* __restrict__ W,
                                               const float* __restrict__ b,
                                               float* __restrict__ out) {
    __shared__ float smem_u[8320];              // sW[32][128] + sP[128][33]
    float (*sW)[128] = reinterpret_cast<float(*)[128]>(smem_u);
    float (*sP)[33]  = reinterpret_cast<float(*)[33]>(smem_u + 4096);

    int t = threadIdx.x;
    int row0 = blockIdx.x * 128;
    int tr = t >> 4, tc = t & 15;

    float acc[8][8];
    #pragma unroll
    for (int i = 0; i < 8; i++)
        #pragma unroll
        for (int j = 0; j < 8; j++) acc[i][j] = 0.f;

    for (int c = 0; c < 4; c++) {
        #pragma unroll
        for (int q = 0; q < 4; q++) {
            int e = t + q * 256;                 // float4 index 0..1023
            int kk = e >> 5, c4 = e & 31;
            ((float4*)&sW[kk][0])[c4] = ((const float4*)W)[(c * 32 + kk) * 32 + c4];
        }
        #pragma unroll
        for (int q = 0; q < 4; q++) {
            int e = t + q * 256;
            int r = e >> 3, c4 = e & 7;
            int gr = row0 + r;
            float4 v = (gr < NN) ? ((const float4*)P)[gr * 32 + c * 8 + c4]
                                 : make_float4(0.f, 0.f, 0.f, 0.f);
            sP[r][c4 * 4 + 0] = v.x;
            sP[r][c4 * 4 + 1] = v.y;
            sP[r][c4 * 4 + 2] = v.z;
            sP[r][c4 * 4 + 3] = v.w;
        }
        __syncthreads();
        #pragma unroll 8
        for (int d = 0; d < 32; d++) {
            float a[8];
            #pragma unroll
            for (int r = 0; r < 8; r++) a[r] = sP[tr * 8 + r][d];
            float4 w0 = *(const float4*)&sW[d][tc * 8];
            float4 w1 = *(const float4*)&sW[d][tc * 8 + 4];
            float wv[8] = {w0.x, w0.y, w0.z, w0.w, w1.x, w1.y, w1.z, w1.w};
            #pragma unroll
            for (int r = 0; r < 8; r++)
                #pragma unroll
                for (int cc = 0; cc < 8; cc++)
                    acc[r][cc] = fmaf(a[r], wv[cc], acc[r][cc]);
        }
        __syncthreads();
    }

    float4 b0 = ((const float4*)b)[tc * 2];
    float4 b1 = ((const float4*)b)[tc * 2 + 1];
    #pragma unroll
    for (int r = 0; r < 8; r++) {
        int gr = row0 + tr * 8 + r;
        if (gr < NN) {
            float4 o0, o1;
            o0.x = fmaxf(acc[r][0] + b0.x, 0.f);
            o0.y = fmaxf(acc[r][1] + b0.y, 0.f);
            o0.z = fmaxf(acc[r][2] + b0.z, 0.f);
            o0.w = fmaxf(acc[r][3] + b0.w, 0.f);
            o1.x = fmaxf(acc[r][4] + b1.x, 0.f);
            o1.y = fmaxf(acc[r][5] + b1.y, 0.f);
            o1.z = fmaxf(acc[r][6] + b1.z, 0.f);
            o1.w = fmaxf(acc[r][7] + b1.w, 0.f);
            ((float4*)&out[gr * 128 + tc * 8])[0] = o0;
            ((float4*)&out[gr * 128 + tc * 8 + 4])[0] = o1;
        }
    }
}

// ---------------- GEMM2 + fused z: z = (P@Wmu+bmu) + noise*exp(P@Wls+bls) -----
__global__ __launch_bounds__(256) void k_gemm2z(const float* __restrict__ P,
                                                const float* __restrict__ Wa,
                                                const float* __restrict__ Wb,
                                                const float* __restrict__ ba,
                                                const float* __restrict__ bb,
                                                const float* __restrict__ noise) {
    __shared__ float smem_u[8320];              // sW+sP, reused as sEx[128][65]
    float (*sW)[128] = reinterpret_cast<float(*)[128]>(smem_u);
    float (*sP)[33]  = reinterpret_cast<float(*)[33]>(smem_u + 4096);
    float (*sEx)[65] = reinterpret_cast<float(*)[65]>(smem_u);

    int t = threadIdx.x;
    int row0 = blockIdx.x * 128;
    int tr = t >> 4, tc = t & 15;

    float acc[8][8];
    #pragma unroll
    for (int i = 0; i < 8; i++)
        #pragma unroll
        for (int j = 0; j < 8; j++) acc[i][j] = 0.f;

    for (int c = 0; c < 4; c++) {
        #pragma unroll
        for (int q = 0; q < 4; q++) {
            int e = t + q * 256;
            int kk = e >> 5, c4 = e & 31;
            float4 v;
            if (c4 < 16) v = ((const float4*)Wa)[(c * 32 + kk) * 16 + c4];
            else         v = ((const float4*)Wb)[(c * 32 + kk) * 16 + (c4 - 16)];
            ((float4*)&sW[kk][0])[c4] = v;
        }
        #pragma unroll
        for (int q = 0; q < 4; q++) {
            int e = t + q * 256;
            int r = e >> 3, c4 = e & 7;
            int gr = row0 + r;
            float4 v = (gr < NN) ? ((const float4*)P)[gr * 32 + c * 8 + c4]
                                 : make_float4(0.f, 0.f, 0.f, 0.f);
            sP[r][c4 * 4 + 0] = v.x;
            sP[r][c4 * 4 + 1] = v.y;
            sP[r][c4 * 4 + 2] = v.z;
            sP[r][c4 * 4 + 3] = v.w;
        }
        __syncthreads();
        #pragma unroll 8
        for (int d = 0; d < 32; d++) {
            float a[8];
            #pragma unroll
            for (int r = 0; r < 8; r++) a[r] = sP[tr * 8 + r][d];
            float4 w0 = *(const float4*)&sW[d][tc * 8];
            float4 w1 = *(const float4*)&sW[d][tc * 8 + 4];
            float wv[8] = {w0.x, w0.y, w0.z, w0.w, w1.x, w1.y, w1.z, w1.w};
            #pragma unroll
            for (int r = 0; r < 8; r++)
                #pragma unroll
                for (int cc = 0; cc < 8; cc++)
                    acc[r][cc] = fmaf(a[r], wv[cc], acc[r][cc]);
        }
        __syncthreads();
    }

    // ls threads (cols 64..127): sEx[lr][o] = exp(ls)*noise
    if (tc >= 8) {
        int ob = tc * 8 - 64;
        #pragma unroll
        for (int r = 0; r < 8; r++) {
            int lr = tr * 8 + r;
            int gr = row0 + lr;
            if (gr < NN) {
                float4 n0 = ((const float4*)(noise + gr * 64 + ob))[0];
                float4 n1 = ((const float4*)(noise + gr * 64 + ob))[1];
                float nv[8] = {n0.x, n0.y, n0.z, n0.w, n1.x, n1.y, n1.z, n1.w};
                #pragma unroll
                for (int cc = 0; cc < 8; cc++) {
                    float ls = acc[r][cc] + bb[ob + cc];
                    sEx[lr][ob + cc] = expf(ls) * nv[cc];
                }
            }
        }
    }
    __syncthreads();
    // mu threads (cols 0..63): z = mu + sEx
    if (tc < 8) {
        int ob = tc * 8;
        #pragma unroll
        for (int r = 0; r < 8; r++) {
            int lr = tr * 8 + r;
            int gr = row0 + lr;
            if (gr < NN) {
                float4 o0, o1;
                o0.x = acc[r][0] + ba[ob + 0] + sEx[lr][ob + 0];
                o0.y = acc[r][1] + ba[ob + 1] + sEx[lr][ob + 1];
                o0.z = acc[r][2] + ba[ob + 2] + sEx[lr][ob + 2];
                o0.w = acc[r][3] + ba[ob + 3] + sEx[lr][ob + 3];
                o1.x = acc[r][4] + ba[ob + 4] + sEx[lr][ob + 4];
                o1.y = acc[r][5] + ba[ob + 5] + sEx[lr][ob + 5];
                o1.z = acc[r][6] + ba[ob + 6] + sEx[lr][ob + 6];
                o1.w = acc[r][7] + ba[ob + 7] + sEx[lr][ob + 7];
                ((float4*)&g_z[gr * 64 + ob])[0] = o0;
                ((float4*)&g_z[gr * 64 + ob + 4])[0] = o1;
            }
        }
    }
}

// ---------------- decoder: logits[e] = dot(z[src], z[dst]) --------------------
__global__ void k_dec(const int* __restrict__ src, const int* __restrict__ dst,
                      float* __restrict__ out) {
    int g = blockIdx.x * (blockDim.x >> 4) + (threadIdx.x >> 4);
    int l = threadIdx.x & 15;
    if (g >= EE) return;
    int s = src[g], d = dst[g];
    float4 a = ((const float4*)g_z)[s * 16 + l];
    float4 b = ((const float4*)g_z)[d * 16 + l];
    float v = a.x * b.x + a.y * b.y + a.z * b.z + a.w * b.w;
    v += __shfl_xor_sync(0xffffffffu, v, 8);
    v += __shfl_xor_sync(0xffffffffu, v, 4);
    v += __shfl_xor_sync(0xffffffffu, v, 2);
    v += __shfl_xor_sync(0xffffffffu, v, 1);
    if (l == 0) out[g] = v;
}

// ---------------- launch -------------------------------------------------------
extern "C" void kernel_launch(void* const* d_in, const int* in_sizes, int n_in,
                              void* d_out, int out_size) {
    const int*   fidx  = (const int*)d_in[0];
    const int*   foff  = (const int*)d_in[1];
    const float* fw    = (const float*)d_in[2];
    const int*   edge  = (const int*)d_in[3];
    const float* noise = (const float*)d_in[4];
    const float* emb   = (const float*)d_in[5];
    const float* W1    = (const float*)d_in[6];
    const float* b1    = (const float*)d_in[7];
    const float* Wmu   = (const float*)d_in[8];
    const float* bmu   = (const float*)d_in[9];
    const float* Wls   = (const float*)d_in[10];
    const float* bls   = (const float*)d_in[11];
    float* out = (float*)d_out;

    const int* src = edge;
    const int* dst = edge + EE;

    float *px = nullptr, *pp = nullptr, *ph = nullptr;
    int* pcnt = nullptr;
    cudaGetSymbolAddress((void**)&px, g_x);
    cudaGetSymbolAddress((void**)&pp, g_p);
    cudaGetSymbolAddress((void**)&ph, g_h);
    cudaGetSymbolAddress((void**)&pcnt, g_cnt);

    // lazily create a side stream + fork/join events (host resources only)
    static cudaStream_t s2 = nullptr;
    static cudaEvent_t evF = nullptr, evJ = nullptr;
    static bool ok = false;
    if (!s2) {
        ok = (cudaStreamCreateWithFlags(&s2, cudaStreamNonBlocking) == cudaSuccess) &&
             (cudaEventCreateWithFlags(&evF, cudaEventDisableTiming) == cudaSuccess) &&
             (cudaEventCreateWithFlags(&evJ, cudaEventDisableTiming) == cudaSuccess);
    }

    cudaStream_t se = ok ? s2 : 0;   // embedding stream
    if (ok) {
        cudaEventRecord(evF, 0);
        cudaStreamWaitEvent(s2, evF, 0);
    }
    // branch B: embedding (independent of CSR build)
    k_embed<<<(NN + 3) / 4, 128, 0, se>>>(fidx, foff, fw, emb);
    if (ok) cudaEventRecord(evJ, s2);

    // branch A: CSR build
    cudaMemsetAsync(pcnt, 0, NN * sizeof(int), 0);
    k_hist<<<(EE / 4 + 255) / 256, 256>>>(dst);
    k_scan1<<<NB, 1024>>>();
    k_scan2<<<1, 64>>>();
    k_scan3<<<(NN + 255) / 256, 256>>>();
    k_scatter<<<(EE / 4 + 255) / 256, 256>>>(src, dst);

    if (ok) cudaStreamWaitEvent(0, evJ, 0);

    k_agg<<<(NN + 3) / 4, 128>>>(px, pp);                          // p1 = A~ x
    k_gemm1<<<(NN + 127) / 128, 256>>>(pp, W1, b1, ph);            // h = relu(p1 W1 + b1)
    k_agg<<<(NN + 3) / 4, 128>>>(ph, pp);                          // p2 = A~ h
    k_gemm2z<<<(NN + 127) / 128, 256>>>(pp, Wmu, Wls, bmu, bls, noise);
    k_dec<<<(EE + 15) / 16, 256>>>(src, dst, out);
}

// round 4
// speedup vs baseline: 2.0991x; 1.1994x over previous
#include <cuda_runtime.h>
#include <cuda_fp16.h>
#include <math.h>

#define NN 50000
#define EE 1600000
#define VV 100000
#define DD 128
#define OO 64
#define TOT (NN*16)
#define NB 49   // ceil(NN/1024)

// ---------------- scratch (static device globals; no allocs allowed) ----------
__device__ int    g_cnt[NN];
__device__ int    g_offs[NN + 1];
__device__ int    g_csr[EE];
__device__ int    g_bsum[64];
__device__ int    g_bpre[64];
__device__ float  g_isqrt[NN];
__device__ float  g_dinv[NN];
__device__ __half g_xh[NN * DD];   // embedding output (fp16)
__device__ float  g_p[NN * DD];    // aggregation output (fp32, GEMM input)
__device__ __half g_hh[NN * DD];   // relu(gemm1) (fp16)
__device__ __half g_zh[NN * OO];   // z (fp16)

// ---------------- CSR build ---------------------------------------------------
__global__ void k_hist(const int* __restrict__ dst) {
    int base = (blockIdx.x * blockDim.x + threadIdx.x) * 4;
    if (base + 4 <= EE) {
        int4 d = *(const int4*)(dst + base);
        atomicAdd(&g_cnt[d.x], 1);
        atomicAdd(&g_cnt[d.y], 1);
        atomicAdd(&g_cnt[d.z], 1);
        atomicAdd(&g_cnt[d.w], 1);
    } else {
        for (int e = base; e < EE; e++) atomicAdd(&g_cnt[dst[e]], 1);
    }
}

__global__ __launch_bounds__(1024) void k_scan1() {
    __shared__ int s[1024];
    int t = threadIdx.x;
    int i = blockIdx.x * 1024 + t;
    int v = (i < NN) ? g_cnt[i] : 0;
    s[t] = v;
    __syncthreads();
    #pragma unroll
    for (int off = 1; off < 1024; off <<= 1) {
        int u = (t >= off) ? s[t - off] : 0;
        __syncthreads();
        s[t] += u;
        __syncthreads();
    }
    if (i < NN) g_offs[i] = s[t] - v;
    if (t == 1023) g_bsum[blockIdx.x] = s[1023];
}

__global__ void k_scan2() {
    __shared__ int s[64];
    int t = threadIdx.x;
    int v = (t < NB) ? g_bsum[t] : 0;
    s[t] = v;
    __syncthreads();
    #pragma unroll
    for (int off = 1; off < 64; off <<= 1) {
        int u = (t >= off) ? s[t - off] : 0;
        __syncthreads();
        s[t] += u;
        __syncthreads();
    }
    g_bpre[t] = s[t] - v;
}

__global__ void k_scan3() {
    int i = blockIdx.x * blockDim.x + threadIdx.x;
    if (i >= NN) return;
    g_offs[i] += g_bpre[i >> 10];
    int c = g_cnt[i];
    float deg = (float)(c + 1);
    g_isqrt[i] = rsqrtf(deg);
    g_dinv[i]  = 1.0f / deg;
    g_cnt[i]   = 0;
    if (i == 0) g_offs[NN] = EE;
}

__global__ void k_scatter(const int* __restrict__ src, const int* __restrict__ dst) {
    int base = (blockIdx.x * blockDim.x + threadIdx.x) * 4;
    if (base + 4 <= EE) {
        int4 d = *(const int4*)(dst + base);
        int4 s = *(const int4*)(src + base);
        int p0 = g_offs[d.x] + atomicAdd(&g_cnt[d.x], 1); g_csr[p0] = s.x;
        int p1 = g_offs[d.y] + atomicAdd(&g_cnt[d.y], 1); g_csr[p1] = s.y;
        int p2 = g_offs[d.z] + atomicAdd(&g_cnt[d.z], 1); g_csr[p2] = s.z;
        int p3 = g_offs[d.w] + atomicAdd(&g_cnt[d.w], 1); g_csr[p3] = s.w;
    } else {
        for (int e = base; e < EE; e++) {
            int d = dst[e];
            int pos = g_offs[d] + atomicAdd(&g_cnt[d], 1);
            g_csr[pos] = src[e];
        }
    }
}

// ---------------- EmbeddingBag(sum, weighted) + L2 normalize -> fp16 ----------
__global__ void k_embed(const int* __restrict__ fidx, const int* __restrict__ foff,
                        const float* __restrict__ fw, const float* __restrict__ emb) {
    int w = (blockIdx.x * blockDim.x + threadIdx.x) >> 5;
    int lane = threadIdx.x & 31;
    if (w >= NN) return;
    int start = foff[w];
    int end = (w + 1 < NN) ? foff[w + 1] : TOT;
    float4 acc = make_float4(0.f, 0.f, 0.f, 0.f);
    int k = start;
    for (; k + 4 <= end; k += 4) {
        int i0 = fidx[k], i1 = fidx[k+1], i2 = fidx[k+2], i3 = fidx[k+3];
        float w0 = fw[k], w1 = fw[k+1], w2 = fw[k+2], w3 = fw[k+3];
        float4 v0 = ((const float4*)emb)[i0 * 32 + lane];
        float4 v1 = ((const float4*)emb)[i1 * 32 + lane];
        float4 v2 = ((const float4*)emb)[i2 * 32 + lane];
        float4 v3 = ((const float4*)emb)[i3 * 32 + lane];
        acc.x = fmaf(w0, v0.x, fmaf(w1, v1.x, fmaf(w2, v2.x, fmaf(w3, v3.x, acc.x))));
        acc.y = fmaf(w0, v0.y, fmaf(w1, v1.y, fmaf(w2, v2.y, fmaf(w3, v3.y, acc.y))));
        acc.z = fmaf(w0, v0.z, fmaf(w1, v1.z, fmaf(w2, v2.z, fmaf(w3, v3.z, acc.z))));
        acc.w = fmaf(w0, v0.w, fmaf(w1, v1.w, fmaf(w2, v2.w, fmaf(w3, v3.w, acc.w))));
    }
    for (; k < end; k++) {
        int idx = fidx[k];
        float wt = fw[k];
        float4 v = ((const float4*)emb)[idx * 32 + lane];
        acc.x = fmaf(wt, v.x, acc.x);
        acc.y = fmaf(wt, v.y, acc.y);
        acc.z = fmaf(wt, v.z, acc.z);
        acc.w = fmaf(wt, v.w, acc.w);
    }
    float ss = acc.x * acc.x + acc.y * acc.y + acc.z * acc.z + acc.w * acc.w;
    for (int o = 16; o > 0; o >>= 1) ss += __shfl_xor_sync(0xffffffffu, ss, o);
    float inv = 1.0f / fmaxf(sqrtf(ss), 1e-12f);
    __half2 h0 = __floats2half2_rn(acc.x * inv, acc.y * inv);
    __half2 h1 = __floats2half2_rn(acc.z * inv, acc.w * inv);
    uint2 u;
    u.x = *(unsigned*)&h0;
    u.y = *(unsigned*)&h1;
    ((uint2*)g_xh)[w * 32 + lane] = u;     // lane owns cols [lane*4, lane*4+4)
}

// ---------------- GCN aggregation: fp16 gather, fp32 accumulate ---------------
__global__ void k_agg(const __half* __restrict__ in, float* __restrict__ out) {
    int w = (blockIdx.x * blockDim.x + threadIdx.x) >> 5;
    int lane = threadIdx.x & 31;
    if (w >= NN) return;
    int lo = g_offs[w], hi = g_offs[w + 1];
    const uint2* in2 = (const uint2*)in;
    float4 acc = make_float4(0.f, 0.f, 0.f, 0.f);
    int p = lo;
    for (; p + 8 <= hi; p += 8) {
        int j[8];
        float wj[8];
        uint2 u[8];
        #pragma unroll
        for (int q = 0; q < 8; q++) j[q] = g_csr[p + q];
        #pragma unroll
        for (int q = 0; q < 8; q++) wj[q] = g_isqrt[j[q]];
        #pragma unroll
        for (int q = 0; q < 8; q++) u[q] = in2[j[q] * 32 + lane];
        #pragma unroll
        for (int q = 0; q < 8; q++) {
            float2 f0 = __half22float2(*(__half2*)&u[q].x);
            float2 f1 = __half22float2(*(__half2*)&u[q].y);
            acc.x = fmaf(wj[q], f0.x, acc.x);
            acc.y = fmaf(wj[q], f0.y, acc.y);
            acc.z = fmaf(wj[q], f1.x, acc.z);
            acc.w = fmaf(wj[q], f1.y, acc.w);
        }
    }
    for (; p < hi; p++) {
        int jj = g_csr[p];
        float wj = g_isqrt[jj];
        uint2 u = in2[jj * 32 + lane];
        float2 f0 = __half22float2(*(__half2*)&u.x);
        float2 f1 = __half22float2(*(__half2*)&u.y);
        acc.x = fmaf(wj, f0.x, acc.x);
        acc.y = fmaf(wj, f0.y, acc.y);
        acc.z = fmaf(wj, f1.x, acc.z);
        acc.w = fmaf(wj, f1.y, acc.w);
    }
    float si = g_isqrt[w], di = g_dinv[w];
    uint2 us = in2[w * 32 + lane];
    float2 s0 = __half22float2(*(__half2*)&us.x);
    float2 s1 = __half22float2(*(__half2*)&us.y);
    float4 o;
    o.x = acc.x * si + s0.x * di;
    o.y = acc.y * si + s0.y * di;
    o.z = acc.z * si + s1.x * di;
    o.w = acc.w * si + s1.y * di;
    ((float4*)out)[w * 32 + lane] = o;
}

// ---------------- GEMM1: h = relu(P @ W1 + b1) -> fp16 -------------------------
__global__ __launch_bounds__(256) void k_gemm1(const float* __restrict__ P,
                                               const float* __restrict__ W,
                                               const float* __restrict__ b,
                                               __half* __restrict__ hout) {
    __shared__ float smem_u[8320];              // sW[32][128] + sP[128][33]
    float (*sW)[128] = reinterpret_cast<float(*)[128]>(smem_u);
    float (*sP)[33]  = reinterpret_cast<float(*)[33]>(smem_u + 4096);

    int t = threadIdx.x;
    int row0 = blockIdx.x * 128;
    int tr = t >> 4, tc = t & 15;

    float acc[8][8];
    #pragma unroll
    for (int i = 0; i < 8; i++)
        #pragma unroll
        for (int j = 0; j < 8; j++) acc[i][j] = 0.f;

    for (int c = 0; c < 4; c++) {
        #pragma unroll
        for (int q = 0; q < 4; q++) {
            int e = t + q * 256;
            int kk = e >> 5, c4 = e & 31;
            ((float4*)&sW[kk][0])[c4] = ((const float4*)W)[(c * 32 + kk) * 32 + c4];
        }
        #pragma unroll
        for (int q = 0; q < 4; q++) {
            int e = t + q * 256;
            int r = e >> 3, c4 = e & 7;
            int gr = row0 + r;
            float4 v = (gr < NN) ? ((const float4*)P)[gr * 32 + c * 8 + c4]
                                 : make_float4(0.f, 0.f, 0.f, 0.f);
            sP[r][c4 * 4 + 0] = v.x;
            sP[r][c4 * 4 + 1] = v.y;
            sP[r][c4 * 4 + 2] = v.z;
            sP[r][c4 * 4 + 3] = v.w;
        }
        __syncthreads();
        #pragma unroll 8
        for (int d = 0; d < 32; d++) {
            float a[8];
            #pragma unroll
            for (int r = 0; r < 8; r++) a[r] = sP[tr * 8 + r][d];
            float4 w0 = *(const float4*)&sW[d][tc * 8];
            float4 w1 = *(const float4*)&sW[d][tc * 8 + 4];
            float wv[8] = {w0.x, w0.y, w0.z, w0.w, w1.x, w1.y, w1.z, w1.w};
            #pragma unroll
            for (int r = 0; r < 8; r++)
                #pragma unroll
                for (int cc = 0; cc < 8; cc++)
                    acc[r][cc] = fmaf(a[r], wv[cc], acc[r][cc]);
        }
        __syncthreads();
    }

    float4 b0 = ((const float4*)b)[tc * 2];
    float4 b1 = ((const float4*)b)[tc * 2 + 1];
    float bv[8] = {b0.x, b0.y, b0.z, b0.w, b1.x, b1.y, b1.z, b1.w};
    #pragma unroll
    for (int r = 0; r < 8; r++) {
        int gr = row0 + tr * 8 + r;
        if (gr < NN) {
            float o[8];
            #pragma unroll
            for (int cc = 0; cc < 8; cc++) o[cc] = fmaxf(acc[r][cc] + bv[cc], 0.f);
            __half2 h0 = __floats2half2_rn(o[0], o[1]);
            __half2 h1 = __floats2half2_rn(o[2], o[3]);
            __half2 h2 = __floats2half2_rn(o[4], o[5]);
            __half2 h3 = __floats2half2_rn(o[6], o[7]);
            uint4 u;
            u.x = *(unsigned*)&h0; u.y = *(unsigned*)&h1;
            u.z = *(unsigned*)&h2; u.w = *(unsigned*)&h3;
            ((uint4*)hout)[gr * 16 + tc] = u;   // 8 halfs at col tc*8
        }
    }
}

// ---------------- GEMM2 + fused z -> fp16 --------------------------------------
__global__ __launch_bounds__(256) void k_gemm2z(const float* __restrict__ P,
                                                const float* __restrict__ Wa,
                                                const float* __restrict__ Wb,
                                                const float* __restrict__ ba,
                                                const float* __restrict__ bb,
                                                const float* __restrict__ noise) {
    __shared__ float smem_u[8320];              // sW+sP, reused as sEx[128][65]
    float (*sW)[128] = reinterpret_cast<float(*)[128]>(smem_u);
    float (*sP)[33]  = reinterpret_cast<float(*)[33]>(smem_u + 4096);
    float (*sEx)[65] = reinterpret_cast<float(*)[65]>(smem_u);

    int t = threadIdx.x;
    int row0 = blockIdx.x * 128;
    int tr = t >> 4, tc = t & 15;

    float acc[8][8];
    #pragma unroll
    for (int i = 0; i < 8; i++)
        #pragma unroll
        for (int j = 0; j < 8; j++) acc[i][j] = 0.f;

    for (int c = 0; c < 4; c++) {
        #pragma unroll
        for (int q = 0; q < 4; q++) {
            int e = t + q * 256;
            int kk = e >> 5, c4 = e & 31;
            float4 v;
            if (c4 < 16) v = ((const float4*)Wa)[(c * 32 + kk) * 16 + c4];
            else         v = ((const float4*)Wb)[(c * 32 + kk) * 16 + (c4 - 16)];
            ((float4*)&sW[kk][0])[c4] = v;
        }
        #pragma unroll
        for (int q = 0; q < 4; q++) {
            int e = t + q * 256;
            int r = e >> 3, c4 = e & 7;
            int gr = row0 + r;
            float4 v = (gr < NN) ? ((const float4*)P)[gr * 32 + c * 8 + c4]
                                 : make_float4(0.f, 0.f, 0.f, 0.f);
            sP[r][c4 * 4 + 0] = v.x;
            sP[r][c4 * 4 + 1] = v.y;
            sP[r][c4 * 4 + 2] = v.z;
            sP[r][c4 * 4 + 3] = v.w;
        }
        __syncthreads();
        #pragma unroll 8
        for (int d = 0; d < 32; d++) {
            float a[8];
            #pragma unroll
            for (int r = 0; r < 8; r++) a[r] = sP[tr * 8 + r][d];
            float4 w0 = *(const float4*)&sW[d][tc * 8];
            float4 w1 = *(const float4*)&sW[d][tc * 8 + 4];
            float wv[8] = {w0.x, w0.y, w0.z, w0.w, w1.x, w1.y, w1.z, w1.w};
            #pragma unroll
            for (int r = 0; r < 8; r++)
                #pragma unroll
                for (int cc = 0; cc < 8; cc++)
                    acc[r][cc] = fmaf(a[r], wv[cc], acc[r][cc]);
        }
        __syncthreads();
    }

    // ls threads (cols 64..127): sEx[lr][o] = exp(ls)*noise
    if (tc >= 8) {
        int ob = tc * 8 - 64;
        #pragma unroll
        for (int r = 0; r < 8; r++) {
            int lr = tr * 8 + r;
            int gr = row0 + lr;
            if (gr < NN) {
                float4 n0 = ((const float4*)(noise + gr * 64 + ob))[0];
                float4 n1 = ((const float4*)(noise + gr * 64 + ob))[1];
                float nv[8] = {n0.x, n0.y, n0.z, n0.w, n1.x, n1.y, n1.z, n1.w};
                #pragma unroll
                for (int cc = 0; cc < 8; cc++) {
                    float ls = acc[r][cc] + bb[ob + cc];
                    sEx[lr][ob + cc] = expf(ls) * nv[cc];
                }
            }
        }
    }
    __syncthreads();
    // mu threads (cols 0..63): z = mu + sEx -> fp16
    if (tc < 8) {
        int ob = tc * 8;
        #pragma unroll
        for (int r = 0; r < 8; r++) {
            int lr = tr * 8 + r;
            int gr = row0 + lr;
            if (gr < NN) {
                float o[8];
                #pragma unroll
                for (int cc = 0; cc < 8; cc++)
                    o[cc] = acc[r][cc] + ba[ob + cc] + sEx[lr][ob + cc];
                __half2 h0 = __floats2half2_rn(o[0], o[1]);
                __half2 h1 = __floats2half2_rn(o[2], o[3]);
                __half2 h2 = __floats2half2_rn(o[4], o[5]);
                __half2 h3 = __floats2half2_rn(o[6], o[7]);
                uint4 u;
                u.x = *(unsigned*)&h0; u.y = *(unsigned*)&h1;
                u.z = *(unsigned*)&h2; u.w = *(unsigned*)&h3;
                ((uint4*)g_zh)[gr * 8 + tc] = u;
            }
        }
    }
}

// ---------------- decoder: logits[e] = dot(z[src], z[dst]), fp16 z ------------
// 8 lanes x uint4 (8 halfs) per edge, fp32 accumulate
__global__ void k_dec(const int* __restrict__ src, const int* __restrict__ dst,
                      float* __restrict__ out) {
    int g = blockIdx.x * (blockDim.x >> 3) + (threadIdx.x >> 3);
    int l = threadIdx.x & 7;
    if (g >= EE) return;
    int s = src[g], d = dst[g];
    uint4 ua = ((const uint4*)g_zh)[s * 8 + l];
    uint4 ub = ((const uint4*)g_zh)[d * 8 + l];
    float v = 0.f;
    const unsigned* pa = &ua.x;
    const unsigned* pb = &ub.x;
    #pragma unroll
    for (int q = 0; q < 4; q++) {
        float2 fa = __half22float2(*(const __half2*)&pa[q]);
        float2 fb = __half22float2(*(const __half2*)&pb[q]);
        v = fmaf(fa.x, fb.x, v);
        v = fmaf(fa.y, fb.y, v);
    }
    v += __shfl_xor_sync(0xffffffffu, v, 4);
    v += __shfl_xor_sync(0xffffffffu, v, 2);
    v += __shfl_xor_sync(0xffffffffu, v, 1);
    if (l == 0) out[g] = v;
}

// ---------------- launch -------------------------------------------------------
extern "C" void kernel_launch(void* const* d_in, const int* in_sizes, int n_in,
                              void* d_out, int out_size) {
    const int*   fidx  = (const int*)d_in[0];
    const int*   foff  = (const int*)d_in[1];
    const float* fw    = (const float*)d_in[2];
    const int*   edge  = (const int*)d_in[3];
    const float* noise = (const float*)d_in[4];
    const float* emb   = (const float*)d_in[5];
    const float* W1    = (const float*)d_in[6];
    const float* b1    = (const float*)d_in[7];
    const float* Wmu   = (const float*)d_in[8];
    const float* bmu   = (const float*)d_in[9];
    const float* Wls   = (const float*)d_in[10];
    const float* bls   = (const float*)d_in[11];
    float* out = (float*)d_out;

    const int* src = edge;
    const int* dst = edge + EE;

    __half *pxh = nullptr, *phh = nullptr;
    float *pp = nullptr;
    int* pcnt = nullptr;
    cudaGetSymbolAddress((void**)&pxh, g_xh);
    cudaGetSymbolAddress((void**)&phh, g_hh);
    cudaGetSymbolAddress((void**)&pp, g_p);
    cudaGetSymbolAddress((void**)&pcnt, g_cnt);

    static cudaStream_t s2 = nullptr;
    static cudaEvent_t evF = nullptr, evJ = nullptr;
    static bool ok = false;
    if (!s2) {
        ok = (cudaStreamCreateWithFlags(&s2, cudaStreamNonBlocking) == cudaSuccess) &&
             (cudaEventCreateWithFlags(&evF, cudaEventDisableTiming) == cudaSuccess) &&
             (cudaEventCreateWithFlags(&evJ, cudaEventDisableTiming) == cudaSuccess);
    }

    cudaStream_t se = ok ? s2 : 0;
    if (ok) {
        cudaEventRecord(evF, 0);
        cudaStreamWaitEvent(s2, evF, 0);
    }
    k_embed<<<(NN + 3) / 4, 128, 0, se>>>(fidx, foff, fw, emb);
    if (ok) cudaEventRecord(evJ, s2);

    cudaMemsetAsync(pcnt, 0, NN * sizeof(int), 0);
    k_hist<<<(EE / 4 + 255) / 256, 256>>>(dst);
    k_scan1<<<NB, 1024>>>();
    k_scan2<<<1, 64>>>();
    k_scan3<<<(NN + 255) / 256, 256>>>();
    k_scatter<<<(EE / 4 + 255) / 256, 256>>>(src, dst);

    if (ok) cudaStreamWaitEvent(0, evJ, 0);

    k_agg<<<(NN + 3) / 4, 128>>>(pxh, pp);                         // p1 = A~ x
    k_gemm1<<<(NN + 127) / 128, 256>>>(pp, W1, b1, phh);           // h (fp16)
    k_agg<<<(NN + 3) / 4, 128>>>(phh, pp);                         // p2 = A~ h
    k_gemm2z<<<(NN + 127) / 128, 256>>>(pp, Wmu, Wls, bmu, bls, noise);
    k_dec<<<(EE + 31) / 32, 256>>>(src, dst, out);
}